// round 7
// baseline (speedup 1.0000x reference)
#include <cuda_runtime.h>
#include <cuda_bf16.h>
#include <mma.h>
#include <cstdint>

using namespace nvcuda;

// Problem constants (fixed by the dataset)
#define NN 50000
#define EE 800000
#define TOT_E (EE + NN)   // edges + self loops = 850000

// ---------------- scratch (no allocations allowed) ----------------
__device__ __align__(16) float g_C1[NN * 256];   // [xl1 | xr1] per node (128+128)
__device__ __align__(16) float g_h [NN * 128];   // layer-1 output after ELU
__device__ __align__(16) float g_C2[NN * 128];   // [xl2 | xr2] per node (64+64)
__device__ int   g_deg[NN];
__device__ int   g_tmp[NN];
__device__ int   g_off[NN + 1];
__device__ int   g_cur[NN];
__device__ int   g_bsum[64];
__device__ int   g_bscan[64];
__device__ int   g_csr[TOT_E];
__device__ int   g_is64;          // 1 if edge_index is int64, 0 if int32

// ---------------- edge-index dtype handling ----------------
__global__ void k_detect(const void* __restrict__ ei) {
    if (threadIdx.x == 0 && blockIdx.x == 0) {
        const long long* p = (const long long*)ei;
        int ok = 1;
        for (int i = 0; i < 64; i++) {
            long long v = p[i];
            if (v < 0 || v >= NN) { ok = 0; break; }
        }
        g_is64 = ok;
    }
}

__device__ __forceinline__ int edge_at(const void* ei, int idx) {
    if (g_is64) return (int)((const long long*)ei)[idx];
    return ((const int*)ei)[idx];
}

// ---------------- CSR build ----------------
__global__ void k_init_deg() {
    int i = blockIdx.x * blockDim.x + threadIdx.x;
    if (i < NN) g_deg[i] = 1;   // self loop
}

__global__ void k_hist(const void* __restrict__ ei) {
    int e = blockIdx.x * blockDim.x + threadIdx.x;
    if (e < EE) {
        int d = edge_at(ei, EE + e);
        atomicAdd(&g_deg[d], 1);
    }
}

__global__ void k_scan1() {
    __shared__ int sh[1024];
    int t = threadIdx.x;
    int i = blockIdx.x * 1024 + t;
    int v = (i < NN) ? g_deg[i] : 0;
    sh[t] = v;
    __syncthreads();
    #pragma unroll
    for (int off = 1; off < 1024; off <<= 1) {
        int x = (t >= off) ? sh[t - off] : 0;
        __syncthreads();
        sh[t] += x;
        __syncthreads();
    }
    if (i < NN) g_tmp[i] = sh[t] - v;
    if (t == 1023) g_bsum[blockIdx.x] = sh[1023];
}

__global__ void k_scan2(int nb) {
    if (threadIdx.x == 0 && blockIdx.x == 0) {
        int run = 0;
        for (int b = 0; b < nb; b++) { g_bscan[b] = run; run += g_bsum[b]; }
    }
}

__global__ void k_scan3() {
    int i = blockIdx.x * 1024 + threadIdx.x;
    if (i < NN) {
        int off = g_tmp[i] + g_bscan[blockIdx.x];
        g_off[i] = off;
        g_cur[i] = off;
        if (i == NN - 1) g_off[NN] = off + g_deg[i];
    }
}

__global__ void k_scatter(const void* __restrict__ ei) {
    int id = blockIdx.x * blockDim.x + threadIdx.x;
    if (id >= TOT_E) return;
    int s, d;
    if (id < EE) { s = edge_at(ei, id); d = edge_at(ei, EE + id); }
    else         { s = d = id - EE; }
    int p = atomicAdd(&g_cur[d], 1);
    g_csr[p] = s;
}

// ---------------- WMMA bf16 GEMM with exact 3-term split ----------------
// C[M x 2*split] = A[M x 128] @ [B0|B1] + bias (bias folded into acc init).
// a = hi + lo in bf16; D = Ah*Wh + Ah*Wl + Al*Wh (Al*Wl ~2^-18, dropped).
// CTA tile 128x128, 8 warps (4x2), warp tile 32x64. K staged in 4 chunks of 32.
// SMEM: As_h/As_l [128][40]b16, Bs_h/Bs_l [128][40]b16 (B transposed: [n][k]),
// BiasT [16][128]f32. Total = 4*10240 + 8192 = 49152 bytes (exactly 48KB, no opt-in).
#define GBM 128
#define GBN 128
#define GBK 32
#define GLDA 40
#define SM_A_BYTES (GBM * GLDA * 2)                 // 10240
#define SM_GEMM_TOTAL (4 * SM_A_BYTES + 16 * GBN * 4)   // 49152

__device__ __forceinline__ void bf16_split(float v, __nv_bfloat16& h, __nv_bfloat16& l) {
    h = __float2bfloat16(v);
    float hf = __bfloat162float(h);
    l = __float2bfloat16(v - hf);
}

template <int LAYER>
__global__ void __launch_bounds__(256)
k_gemm_mma(const float* __restrict__ Ain,
           const float* __restrict__ B0, const float* __restrict__ B1,
           const float* __restrict__ bias0, const float* __restrict__ bias1)
{
    extern __shared__ char smem[];
    __nv_bfloat16* As_h = (__nv_bfloat16*)(smem);
    __nv_bfloat16* As_l = (__nv_bfloat16*)(smem + SM_A_BYTES);
    __nv_bfloat16* Bs_h = (__nv_bfloat16*)(smem + 2 * SM_A_BYTES);
    __nv_bfloat16* Bs_l = (__nv_bfloat16*)(smem + 3 * SM_A_BYTES);
    float* BiasT = (float*)(smem + 4 * SM_A_BYTES);   // [16][128], rows identical

    const float* A  = (LAYER == 1) ? Ain : g_h;
    float* C        = (LAYER == 1) ? g_C1 : g_C2;
    const int split = (LAYER == 1) ? 128 : 64;
    const int NB    = 2 * split;

    int tid = threadIdx.x;
    int wid = tid >> 5;
    int lane = tid & 31;
    int rowBase = blockIdx.x * GBM;
    int colBase = blockIdx.y * GBN;
    int wm = (wid & 3) * 32;
    int wn = (wid >> 2) * 64;

    // Build bias tile (16 identical rows)
    #pragma unroll
    for (int it = 0; it < 8; it++) {
        int idx = tid + it * 256;
        int c = idx & 127, r = idx >> 7;
        int col = colBase + c;
        float bv = (col < split) ? bias0[col] : bias1[col - split];
        BiasT[r * 128 + c] = bv;
    }
    __syncthreads();

    wmma::fragment<wmma::accumulator, 16, 16, 16, float> acc[2][4];
    #pragma unroll
    for (int m = 0; m < 2; m++)
        #pragma unroll
        for (int n = 0; n < 4; n++)
            wmma::load_matrix_sync(acc[m][n], &BiasT[wn + 16 * n], 128, wmma::mem_row_major);

    #pragma unroll
    for (int stage = 0; stage < 4; stage++) {
        int kb = stage * GBK;
        if (stage) __syncthreads();   // prior-stage mma reads done before overwrite

        // A tile: 128 rows x 32 k (fp32) -> bf16 hi/lo
        #pragma unroll
        for (int it = 0; it < 4; it++) {
            int idx = tid + it * 256;        // 1024 float4 items
            int kq = idx & 7, r = idx >> 3;
            int gr = rowBase + r;
            float4 v = make_float4(0.f, 0.f, 0.f, 0.f);
            if (gr < NN) v = *(const float4*)&A[gr * 128 + kb + kq * 4];
            float vs[4] = {v.x, v.y, v.z, v.w};
            #pragma unroll
            for (int j = 0; j < 4; j++) {
                __nv_bfloat16 h, l;
                bf16_split(vs[j], h, l);
                As_h[r * GLDA + kq * 4 + j] = h;
                As_l[r * GLDA + kq * 4 + j] = l;
            }
        }
        // B tile transposed: Bs[n][k] = W[kb+k][colBase+n]
        #pragma unroll
        for (int it = 0; it < 4; it++) {
            int idx = tid + it * 256;        // 1024 float4 items
            int k = idx >> 5, nq = idx & 31; // k in [0,32)
            int gn = colBase + nq * 4;
            const float* W = (gn < split) ? B0 : B1;
            int wc = (gn < split) ? gn : gn - split;
            float4 v = *(const float4*)&W[(kb + k) * split + wc];
            float vs[4] = {v.x, v.y, v.z, v.w};
            #pragma unroll
            for (int j = 0; j < 4; j++) {
                __nv_bfloat16 h, l;
                bf16_split(vs[j], h, l);
                Bs_h[(nq * 4 + j) * GLDA + k] = h;
                Bs_l[(nq * 4 + j) * GLDA + k] = l;
            }
        }
        __syncthreads();

        #pragma unroll
        for (int ks = 0; ks < 2; ks++) {
            wmma::fragment<wmma::matrix_a, 16, 16, 16, __nv_bfloat16, wmma::row_major> ah[2], al[2];
            #pragma unroll
            for (int m = 0; m < 2; m++) {
                wmma::load_matrix_sync(ah[m], &As_h[(wm + 16 * m) * GLDA + ks * 16], GLDA);
                wmma::load_matrix_sync(al[m], &As_l[(wm + 16 * m) * GLDA + ks * 16], GLDA);
            }
            #pragma unroll
            for (int n = 0; n < 4; n++) {
                wmma::fragment<wmma::matrix_b, 16, 16, 16, __nv_bfloat16, wmma::col_major> bh, bl;
                wmma::load_matrix_sync(bh, &Bs_h[(wn + 16 * n) * GLDA + ks * 16], GLDA);
                wmma::load_matrix_sync(bl, &Bs_l[(wn + 16 * n) * GLDA + ks * 16], GLDA);
                #pragma unroll
                for (int m = 0; m < 2; m++) {
                    wmma::mma_sync(acc[m][n], ah[m], bh, acc[m][n]);
                    wmma::mma_sync(acc[m][n], ah[m], bl, acc[m][n]);
                    wmma::mma_sync(acc[m][n], al[m], bh, acc[m][n]);
                }
            }
        }
    }

    if (rowBase + GBM <= NN) {
        // full tile: direct global stores
        #pragma unroll
        for (int m = 0; m < 2; m++)
            #pragma unroll
            for (int n = 0; n < 4; n++) {
                int gr = rowBase + wm + 16 * m;
                wmma::store_matrix_sync(&C[(size_t)gr * NB + colBase + wn + 16 * n],
                                        acc[m][n], NB, wmma::mem_row_major);
            }
    } else {
        // tail tile: per-warp smem staging, guarded copy
        __syncthreads();                              // all mma smem reads done
        float* scr = (float*)smem + wid * 16 * 20;    // 16 rows x ld 20 per warp
        #pragma unroll
        for (int m = 0; m < 2; m++)
            #pragma unroll
            for (int n = 0; n < 4; n++) {
                wmma::store_matrix_sync(scr, acc[m][n], 20, wmma::mem_row_major);
                __syncwarp();
                int r = lane >> 1, c0 = (lane & 1) * 8;
                int gr = rowBase + wm + 16 * m + r;
                if (gr < NN) {
                    int gc = colBase + wn + 16 * n + c0;
                    #pragma unroll
                    for (int j = 0; j < 8; j++)
                        C[(size_t)gr * NB + gc + j] = scr[r * 20 + c0 + j];
                }
                __syncwarp();
            }
    }
}

// ---------------- layer-1 edge pass: warp per node, 8 heads x 16 dims ----------------
__global__ void __launch_bounds__(256)
k_edge1(const float* __restrict__ att1, const float* __restrict__ bias1)
{
    int warp = (blockIdx.x * blockDim.x + threadIdx.x) >> 5;
    int lane = threadIdx.x & 31;
    if (warp >= NN) return;
    int node = warp;
    int sub = lane & 3;
    int head = lane >> 2;

    float4 av = *(const float4*)&att1[head * 16 + sub * 4];
    float4 xr = *(const float4*)&g_C1[node * 256 + 128 + lane * 4];

    float m = -3.4e38f, s = 0.f;
    float4 acc = make_float4(0.f, 0.f, 0.f, 0.f);

    int beg = g_off[node], end = g_off[node + 1];
    for (int i = beg; i < end; i++) {
        int src = g_csr[i];
        float4 xl = *(const float4*)&g_C1[src * 256 + lane * 4];
        float tx0 = xl.x + xr.x, tx1 = xl.y + xr.y, tx2 = xl.z + xr.z, tx3 = xl.w + xr.w;
        tx0 = tx0 > 0.f ? tx0 : 0.2f * tx0;
        tx1 = tx1 > 0.f ? tx1 : 0.2f * tx1;
        tx2 = tx2 > 0.f ? tx2 : 0.2f * tx2;
        tx3 = tx3 > 0.f ? tx3 : 0.2f * tx3;
        float p = tx0 * av.x + tx1 * av.y + tx2 * av.z + tx3 * av.w;
        p += __shfl_xor_sync(0xffffffffu, p, 1);
        p += __shfl_xor_sync(0xffffffffu, p, 2);
        float nm = fmaxf(m, p);
        float sc = __expf(m - nm);
        float w  = __expf(p - nm);
        s = s * sc + w;
        acc.x = acc.x * sc + w * xl.x;
        acc.y = acc.y * sc + w * xl.y;
        acc.z = acc.z * sc + w * xl.z;
        acc.w = acc.w * sc + w * xl.w;
        m = nm;
    }
    float inv = 1.f / s;
    float4 bv = *(const float4*)&bias1[lane * 4];
    float o0 = acc.x * inv + bv.x;
    float o1 = acc.y * inv + bv.y;
    float o2 = acc.z * inv + bv.z;
    float o3 = acc.w * inv + bv.w;
    o0 = o0 > 0.f ? o0 : expm1f(o0);
    o1 = o1 > 0.f ? o1 : expm1f(o1);
    o2 = o2 > 0.f ? o2 : expm1f(o2);
    o3 = o3 > 0.f ? o3 : expm1f(o3);
    *(float4*)&g_h[node * 128 + lane * 4] = make_float4(o0, o1, o2, o3);
}

// ---------------- layer-2 edge pass: warp per node, 1 head x 64 dims ----------------
__global__ void __launch_bounds__(256)
k_edge2(const float* __restrict__ att2, const float* __restrict__ bias2,
        float* __restrict__ out)
{
    int warp = (blockIdx.x * blockDim.x + threadIdx.x) >> 5;
    int lane = threadIdx.x & 31;
    if (warp >= NN) return;
    int node = warp;

    float2 av = *(const float2*)&att2[lane * 2];
    float2 xr = *(const float2*)&g_C2[node * 128 + 64 + lane * 2];

    float m = -3.4e38f, s = 0.f;
    float2 acc = make_float2(0.f, 0.f);

    int beg = g_off[node], end = g_off[node + 1];
    for (int i = beg; i < end; i++) {
        int src = g_csr[i];
        float2 xl = *(const float2*)&g_C2[src * 128 + lane * 2];
        float t0 = xl.x + xr.x, t1 = xl.y + xr.y;
        t0 = t0 > 0.f ? t0 : 0.2f * t0;
        t1 = t1 > 0.f ? t1 : 0.2f * t1;
        float p = t0 * av.x + t1 * av.y;
        p += __shfl_xor_sync(0xffffffffu, p, 1);
        p += __shfl_xor_sync(0xffffffffu, p, 2);
        p += __shfl_xor_sync(0xffffffffu, p, 4);
        p += __shfl_xor_sync(0xffffffffu, p, 8);
        p += __shfl_xor_sync(0xffffffffu, p, 16);
        float nm = fmaxf(m, p);
        float sc = __expf(m - nm);
        float w  = __expf(p - nm);
        s = s * sc + w;
        acc.x = acc.x * sc + w * xl.x;
        acc.y = acc.y * sc + w * xl.y;
        m = nm;
    }
    float inv = 1.f / s;
    float2 bv = *(const float2*)&bias2[lane * 2];
    float2 o;
    o.x = acc.x * inv + bv.x;
    o.y = acc.y * inv + bv.y;
    *(float2*)&out[node * 64 + lane * 2] = o;
}

// ---------------- launch ----------------
extern "C" void kernel_launch(void* const* d_in, const int* in_sizes, int n_in,
                              void* d_out, int out_size)
{
    const float* x     = (const float*)d_in[0];
    const void*  ei    = d_in[1];
    const float* W1l   = (const float*)d_in[2];
    const float* b1l   = (const float*)d_in[3];
    const float* W1r   = (const float*)d_in[4];
    const float* b1r   = (const float*)d_in[5];
    const float* att1  = (const float*)d_in[6];
    const float* bias1 = (const float*)d_in[7];
    const float* W2l   = (const float*)d_in[8];
    const float* b2l   = (const float*)d_in[9];
    const float* W2r   = (const float*)d_in[10];
    const float* b2r   = (const float*)d_in[11];
    const float* att2  = (const float*)d_in[12];
    const float* bias2 = (const float*)d_in[13];
    float* out = (float*)d_out;

    // CSR build
    k_detect<<<1, 32>>>(ei);
    k_init_deg<<<(NN + 255) / 256, 256>>>();
    k_hist<<<(EE + 255) / 256, 256>>>(ei);
    int nsb = (NN + 1023) / 1024;           // 49
    k_scan1<<<nsb, 1024>>>();
    k_scan2<<<1, 32>>>(nsb);
    k_scan3<<<nsb, 1024>>>();
    k_scatter<<<(TOT_E + 255) / 256, 256>>>(ei);

    // layer 1: C1 = [x@W1l + b1l | x@W1r + b1r]  (N x 256)
    {
        dim3 grid((NN + 127) / 128, 2);
        k_gemm_mma<1><<<grid, 256, SM_GEMM_TOTAL>>>(x, W1l, W1r, b1l, b1r);
    }
    k_edge1<<<(NN * 32 + 255) / 256, 256>>>(att1, bias1);

    // layer 2: C2 = [h@W2l + b2l | h@W2r + b2r]  (N x 128)
    {
        dim3 grid((NN + 127) / 128, 1);
        k_gemm_mma<2><<<grid, 256, SM_GEMM_TOTAL>>>(nullptr, W2l, W2r, b2l, b2r);
    }
    k_edge2<<<(NN * 32 + 255) / 256, 256>>>(att2, bias2, out);

    (void)in_sizes; (void)n_in; (void)out_size;
}

// round 8
// speedup vs baseline: 1.2661x; 1.2661x over previous
#include <cuda_runtime.h>
#include <cuda_bf16.h>
#include <mma.h>
#include <cstdint>

using namespace nvcuda;

// Problem constants (fixed by the dataset)
#define NN 50000
#define EE 800000
#define TOT_E (EE + NN)   // edges + self loops = 850000

// ---------------- scratch (no allocations allowed) ----------------
__device__ __align__(16) float g_C1[NN * 256];   // [xl1 | xr1] per node (128+128)
__device__ __align__(16) float g_h [NN * 128];   // layer-1 output after ELU
__device__ __align__(16) float g_C2[NN * 128];   // [xl2 | xr2] per node (64+64)
__device__ __align__(16) __nv_bfloat16 g_Ah[NN * 128];   // A hi (bf16 split)
__device__ __align__(16) __nv_bfloat16 g_Al[NN * 128];   // A lo
__device__ __align__(16) __nv_bfloat16 g_Bh[256 * 128];  // W transposed [n][k] hi
__device__ __align__(16) __nv_bfloat16 g_Bl[256 * 128];  // W transposed [n][k] lo
__device__ int   g_deg[NN];
__device__ int   g_tmp[NN];
__device__ int   g_off[NN + 1];
__device__ int   g_cur[NN];
__device__ int   g_bsum[64];
__device__ int   g_bscan[64];
__device__ int   g_csr[TOT_E];
__device__ int   g_is64;          // 1 if edge_index is int64, 0 if int32

// ---------------- edge-index dtype handling ----------------
__global__ void k_detect(const void* __restrict__ ei) {
    if (threadIdx.x == 0 && blockIdx.x == 0) {
        const long long* p = (const long long*)ei;
        int ok = 1;
        for (int i = 0; i < 64; i++) {
            long long v = p[i];
            if (v < 0 || v >= NN) { ok = 0; break; }
        }
        g_is64 = ok;
    }
}

__device__ __forceinline__ int edge_at(const void* ei, int idx) {
    if (g_is64) return (int)((const long long*)ei)[idx];
    return ((const int*)ei)[idx];
}

// ---------------- CSR build ----------------
__global__ void k_init_deg() {
    int i = blockIdx.x * blockDim.x + threadIdx.x;
    if (i < NN) g_deg[i] = 1;   // self loop
}

__global__ void k_hist(const void* __restrict__ ei) {
    int e = blockIdx.x * blockDim.x + threadIdx.x;
    if (e < EE) {
        int d = edge_at(ei, EE + e);
        atomicAdd(&g_deg[d], 1);
    }
}

__global__ void k_scan1() {
    __shared__ int sh[1024];
    int t = threadIdx.x;
    int i = blockIdx.x * 1024 + t;
    int v = (i < NN) ? g_deg[i] : 0;
    sh[t] = v;
    __syncthreads();
    #pragma unroll
    for (int off = 1; off < 1024; off <<= 1) {
        int x = (t >= off) ? sh[t - off] : 0;
        __syncthreads();
        sh[t] += x;
        __syncthreads();
    }
    if (i < NN) g_tmp[i] = sh[t] - v;
    if (t == 1023) g_bsum[blockIdx.x] = sh[1023];
}

__global__ void k_scan2(int nb) {
    if (threadIdx.x == 0 && blockIdx.x == 0) {
        int run = 0;
        for (int b = 0; b < nb; b++) { g_bscan[b] = run; run += g_bsum[b]; }
    }
}

__global__ void k_scan3() {
    int i = blockIdx.x * 1024 + threadIdx.x;
    if (i < NN) {
        int off = g_tmp[i] + g_bscan[blockIdx.x];
        g_off[i] = off;
        g_cur[i] = off;
        if (i == NN - 1) g_off[NN] = off + g_deg[i];
    }
}

__global__ void k_scatter(const void* __restrict__ ei) {
    int id = blockIdx.x * blockDim.x + threadIdx.x;
    if (id >= TOT_E) return;
    int s, d;
    if (id < EE) { s = edge_at(ei, id); d = edge_at(ei, EE + id); }
    else         { s = d = id - EE; }
    int p = atomicAdd(&g_cur[d], 1);
    g_csr[p] = s;
}

// ---------------- precompute bf16 hi/lo splits ----------------
__device__ __forceinline__ void bf16_split(float v, __nv_bfloat16& h, __nv_bfloat16& l) {
    h = __float2bfloat16(v);
    l = __float2bfloat16(v - __bfloat162float(h));
}

template <int LAYER>
__global__ void k_convA(const float* __restrict__ Ain) {
    const float* A = (LAYER == 1) ? Ain : g_h;
    int i = blockIdx.x * blockDim.x + threadIdx.x;   // one per 4 elements
    if (i >= NN * 32) return;
    float4 v = *(const float4*)&A[i * 4];
    __nv_bfloat16 h[4], l[4];
    bf16_split(v.x, h[0], l[0]);
    bf16_split(v.y, h[1], l[1]);
    bf16_split(v.z, h[2], l[2]);
    bf16_split(v.w, h[3], l[3]);
    *(uint2*)&g_Ah[i * 4] = *(uint2*)h;
    *(uint2*)&g_Al[i * 4] = *(uint2*)l;
}

template <int LAYER>
__global__ void k_convW(const float* __restrict__ B0, const float* __restrict__ B1) {
    const int split = (LAYER == 1) ? 128 : 64;
    const int NB = 2 * split;
    int idx = blockIdx.x * blockDim.x + threadIdx.x;  // n fastest (coalesced W read)
    if (idx >= NB * 128) return;
    int n = idx % NB, k = idx / NB;
    const float* W = (n < split) ? B0 : B1;
    int wc = (n < split) ? n : n - split;
    float v = W[k * split + wc];
    __nv_bfloat16 h, l;
    bf16_split(v, h, l);
    g_Bh[n * 128 + k] = h;
    g_Bl[n * 128 + k] = l;
}

// ---------------- WMMA bf16 GEMM (preconverted operands) ----------------
// C[M x NB] = A[M x 128] @ W + bias. D = Ah*Wh + Ah*Wl + Al*Wh (Al*Wl dropped).
// CTA tile 128x128, 8 warps (4x2), warp tile 32x64, 4 K-stages of 32.
// SMEM = 4*10240 + 8192 = 49152 bytes (48KB, no opt-in needed).
#define GBM 128
#define GBN 128
#define GBK 32
#define GLDA 40
#define SM_A_BYTES (GBM * GLDA * 2)                 // 10240
#define SM_GEMM_TOTAL (4 * SM_A_BYTES + 16 * GBN * 4)   // 49152

template <int LAYER>
__global__ void __launch_bounds__(256)
k_gemm_mma(const float* __restrict__ bias0, const float* __restrict__ bias1)
{
    extern __shared__ char smem[];
    __nv_bfloat16* As_h = (__nv_bfloat16*)(smem);
    __nv_bfloat16* As_l = (__nv_bfloat16*)(smem + SM_A_BYTES);
    __nv_bfloat16* Bs_h = (__nv_bfloat16*)(smem + 2 * SM_A_BYTES);
    __nv_bfloat16* Bs_l = (__nv_bfloat16*)(smem + 3 * SM_A_BYTES);
    float* BiasT = (float*)(smem + 4 * SM_A_BYTES);   // [16][128], rows identical

    float* C        = (LAYER == 1) ? g_C1 : g_C2;
    const int split = (LAYER == 1) ? 128 : 64;
    const int NB    = 2 * split;

    int tid = threadIdx.x;
    int wid = tid >> 5;
    int lane = tid & 31;
    int rowBase = blockIdx.x * GBM;
    int colBase = blockIdx.y * GBN;
    int wm = (wid & 3) * 32;
    int wn = (wid >> 2) * 64;

    // Build bias tile (16 identical rows)
    #pragma unroll
    for (int it = 0; it < 8; it++) {
        int idx = tid + it * 256;
        int c = idx & 127, r = idx >> 7;
        int col = colBase + c;
        float bv = (col < split) ? bias0[col] : bias1[col - split];
        BiasT[r * 128 + c] = bv;
    }
    __syncthreads();

    wmma::fragment<wmma::accumulator, 16, 16, 16, float> acc[2][4];
    #pragma unroll
    for (int m = 0; m < 2; m++)
        #pragma unroll
        for (int n = 0; n < 4; n++)
            wmma::load_matrix_sync(acc[m][n], &BiasT[wn + 16 * n], 128, wmma::mem_row_major);

    #pragma unroll
    for (int stage = 0; stage < 4; stage++) {
        int kb = stage * GBK;
        if (stage) __syncthreads();   // prior-stage mma reads done before overwrite

        // A tile: 128 rows x 32 k, bf16 hi+lo, pure uint4 traffic
        #pragma unroll
        for (int it = 0; it < 2; it++) {
            int idx = tid + it * 256;        // 512 uint4 items
            int kq = idx & 3, r = idx >> 2;
            int gr = rowBase + r;
            uint4 vh = make_uint4(0, 0, 0, 0), vl = make_uint4(0, 0, 0, 0);
            if (gr < NN) {
                vh = *(const uint4*)&g_Ah[gr * 128 + kb + kq * 8];
                vl = *(const uint4*)&g_Al[gr * 128 + kb + kq * 8];
            }
            *(uint4*)&As_h[r * GLDA + kq * 8] = vh;
            *(uint4*)&As_l[r * GLDA + kq * 8] = vl;
        }
        // B tile: 128 n-rows x 32 k from pre-transposed g_Bh/g_Bl
        #pragma unroll
        for (int it = 0; it < 2; it++) {
            int idx = tid + it * 256;        // 512 uint4 items
            int kq = idx & 3, n = idx >> 2;
            int gn = colBase + n;
            uint4 vh = *(const uint4*)&g_Bh[gn * 128 + kb + kq * 8];
            uint4 vl = *(const uint4*)&g_Bl[gn * 128 + kb + kq * 8];
            *(uint4*)&Bs_h[n * GLDA + kq * 8] = vh;
            *(uint4*)&Bs_l[n * GLDA + kq * 8] = vl;
        }
        __syncthreads();

        #pragma unroll
        for (int ks = 0; ks < 2; ks++) {
            wmma::fragment<wmma::matrix_a, 16, 16, 16, __nv_bfloat16, wmma::row_major> ah[2], al[2];
            #pragma unroll
            for (int m = 0; m < 2; m++) {
                wmma::load_matrix_sync(ah[m], &As_h[(wm + 16 * m) * GLDA + ks * 16], GLDA);
                wmma::load_matrix_sync(al[m], &As_l[(wm + 16 * m) * GLDA + ks * 16], GLDA);
            }
            #pragma unroll
            for (int n = 0; n < 4; n++) {
                wmma::fragment<wmma::matrix_b, 16, 16, 16, __nv_bfloat16, wmma::col_major> bh, bl;
                wmma::load_matrix_sync(bh, &Bs_h[(wn + 16 * n) * GLDA + ks * 16], GLDA);
                wmma::load_matrix_sync(bl, &Bs_l[(wn + 16 * n) * GLDA + ks * 16], GLDA);
                #pragma unroll
                for (int m = 0; m < 2; m++) {
                    wmma::mma_sync(acc[m][n], ah[m], bh, acc[m][n]);
                    wmma::mma_sync(acc[m][n], ah[m], bl, acc[m][n]);
                    wmma::mma_sync(acc[m][n], al[m], bh, acc[m][n]);
                }
            }
        }
    }

    if (rowBase + GBM <= NN) {
        #pragma unroll
        for (int m = 0; m < 2; m++)
            #pragma unroll
            for (int n = 0; n < 4; n++) {
                int gr = rowBase + wm + 16 * m;
                wmma::store_matrix_sync(&C[(size_t)gr * NB + colBase + wn + 16 * n],
                                        acc[m][n], NB, wmma::mem_row_major);
            }
    } else {
        // tail tile: per-warp smem staging, guarded copy
        __syncthreads();
        float* scr = (float*)smem + wid * 16 * 20;
        #pragma unroll
        for (int m = 0; m < 2; m++)
            #pragma unroll
            for (int n = 0; n < 4; n++) {
                wmma::store_matrix_sync(scr, acc[m][n], 20, wmma::mem_row_major);
                __syncwarp();
                int r = lane >> 1, c0 = (lane & 1) * 8;
                int gr = rowBase + wm + 16 * m + r;
                if (gr < NN) {
                    int gc = colBase + wn + 16 * n + c0;
                    #pragma unroll
                    for (int j = 0; j < 8; j++)
                        C[(size_t)gr * NB + gc + j] = scr[r * 20 + c0 + j];
                }
                __syncwarp();
            }
    }
}

// ---------------- layer-1 edge pass: warp per node, 8 heads x 16 dims ----------------
__global__ void __launch_bounds__(256)
k_edge1(const float* __restrict__ att1, const float* __restrict__ bias1)
{
    int warp = (blockIdx.x * blockDim.x + threadIdx.x) >> 5;
    int lane = threadIdx.x & 31;
    if (warp >= NN) return;
    int node = warp;
    int sub = lane & 3;
    int head = lane >> 2;

    float4 av = *(const float4*)&att1[head * 16 + sub * 4];
    float4 xr = *(const float4*)&g_C1[node * 256 + 128 + lane * 4];

    float m = -3.4e38f, s = 0.f;
    float4 acc = make_float4(0.f, 0.f, 0.f, 0.f);

    int beg = g_off[node], end = g_off[node + 1];
    for (int i = beg; i < end; i++) {
        int src = g_csr[i];
        float4 xl = *(const float4*)&g_C1[src * 256 + lane * 4];
        float tx0 = xl.x + xr.x, tx1 = xl.y + xr.y, tx2 = xl.z + xr.z, tx3 = xl.w + xr.w;
        tx0 = tx0 > 0.f ? tx0 : 0.2f * tx0;
        tx1 = tx1 > 0.f ? tx1 : 0.2f * tx1;
        tx2 = tx2 > 0.f ? tx2 : 0.2f * tx2;
        tx3 = tx3 > 0.f ? tx3 : 0.2f * tx3;
        float p = tx0 * av.x + tx1 * av.y + tx2 * av.z + tx3 * av.w;
        p += __shfl_xor_sync(0xffffffffu, p, 1);
        p += __shfl_xor_sync(0xffffffffu, p, 2);
        float nm = fmaxf(m, p);
        float sc = __expf(m - nm);
        float w  = __expf(p - nm);
        s = s * sc + w;
        acc.x = acc.x * sc + w * xl.x;
        acc.y = acc.y * sc + w * xl.y;
        acc.z = acc.z * sc + w * xl.z;
        acc.w = acc.w * sc + w * xl.w;
        m = nm;
    }
    float inv = 1.f / s;
    float4 bv = *(const float4*)&bias1[lane * 4];
    float o0 = acc.x * inv + bv.x;
    float o1 = acc.y * inv + bv.y;
    float o2 = acc.z * inv + bv.z;
    float o3 = acc.w * inv + bv.w;
    o0 = o0 > 0.f ? o0 : expm1f(o0);
    o1 = o1 > 0.f ? o1 : expm1f(o1);
    o2 = o2 > 0.f ? o2 : expm1f(o2);
    o3 = o3 > 0.f ? o3 : expm1f(o3);
    *(float4*)&g_h[node * 128 + lane * 4] = make_float4(o0, o1, o2, o3);
}

// ---------------- layer-2 edge pass: warp per node, 1 head x 64 dims ----------------
__global__ void __launch_bounds__(256)
k_edge2(const float* __restrict__ att2, const float* __restrict__ bias2,
        float* __restrict__ out)
{
    int warp = (blockIdx.x * blockDim.x + threadIdx.x) >> 5;
    int lane = threadIdx.x & 31;
    if (warp >= NN) return;
    int node = warp;

    float2 av = *(const float2*)&att2[lane * 2];
    float2 xr = *(const float2*)&g_C2[node * 128 + 64 + lane * 2];

    float m = -3.4e38f, s = 0.f;
    float2 acc = make_float2(0.f, 0.f);

    int beg = g_off[node], end = g_off[node + 1];
    for (int i = beg; i < end; i++) {
        int src = g_csr[i];
        float2 xl = *(const float2*)&g_C2[src * 128 + lane * 2];
        float t0 = xl.x + xr.x, t1 = xl.y + xr.y;
        t0 = t0 > 0.f ? t0 : 0.2f * t0;
        t1 = t1 > 0.f ? t1 : 0.2f * t1;
        float p = t0 * av.x + t1 * av.y;
        p += __shfl_xor_sync(0xffffffffu, p, 1);
        p += __shfl_xor_sync(0xffffffffu, p, 2);
        p += __shfl_xor_sync(0xffffffffu, p, 4);
        p += __shfl_xor_sync(0xffffffffu, p, 8);
        p += __shfl_xor_sync(0xffffffffu, p, 16);
        float nm = fmaxf(m, p);
        float sc = __expf(m - nm);
        float w  = __expf(p - nm);
        s = s * sc + w;
        acc.x = acc.x * sc + w * xl.x;
        acc.y = acc.y * sc + w * xl.y;
        m = nm;
    }
    float inv = 1.f / s;
    float2 bv = *(const float2*)&bias2[lane * 2];
    float2 o;
    o.x = acc.x * inv + bv.x;
    o.y = acc.y * inv + bv.y;
    *(float2*)&out[node * 64 + lane * 2] = o;
}

// ---------------- launch ----------------
extern "C" void kernel_launch(void* const* d_in, const int* in_sizes, int n_in,
                              void* d_out, int out_size)
{
    const float* x     = (const float*)d_in[0];
    const void*  ei    = d_in[1];
    const float* W1l   = (const float*)d_in[2];
    const float* b1l   = (const float*)d_in[3];
    const float* W1r   = (const float*)d_in[4];
    const float* b1r   = (const float*)d_in[5];
    const float* att1  = (const float*)d_in[6];
    const float* bias1 = (const float*)d_in[7];
    const float* W2l   = (const float*)d_in[8];
    const float* b2l   = (const float*)d_in[9];
    const float* W2r   = (const float*)d_in[10];
    const float* b2r   = (const float*)d_in[11];
    const float* att2  = (const float*)d_in[12];
    const float* bias2 = (const float*)d_in[13];
    float* out = (float*)d_out;

    // CSR build
    k_detect<<<1, 32>>>(ei);
    k_init_deg<<<(NN + 255) / 256, 256>>>();
    k_hist<<<(EE + 255) / 256, 256>>>(ei);
    int nsb = (NN + 1023) / 1024;           // 49
    k_scan1<<<nsb, 1024>>>();
    k_scan2<<<1, 32>>>(nsb);
    k_scan3<<<nsb, 1024>>>();
    k_scatter<<<(TOT_E + 255) / 256, 256>>>(ei);

    // layer 1
    k_convA<1><<<(NN * 32 + 255) / 256, 256>>>(x);
    k_convW<1><<<(256 * 128 + 255) / 256, 256>>>(W1l, W1r);
    {
        dim3 grid((NN + 127) / 128, 2);
        k_gemm_mma<1><<<grid, 256, SM_GEMM_TOTAL>>>(b1l, b1r);
    }
    k_edge1<<<(NN * 32 + 255) / 256, 256>>>(att1, bias1);

    // layer 2
    k_convA<2><<<(NN * 32 + 255) / 256, 256>>>(nullptr);
    k_convW<2><<<(128 * 128 + 255) / 256, 256>>>(W2l, W2r);
    {
        dim3 grid((NN + 127) / 128, 1);
        k_gemm_mma<2><<<grid, 256, SM_GEMM_TOTAL>>>(b2l, b2r);
    }
    k_edge2<<<(NN * 32 + 255) / 256, 256>>>(att2, bias2, out);

    (void)in_sizes; (void)n_in; (void)out_size;
}

// round 9
// speedup vs baseline: 1.4178x; 1.1198x over previous
#include <cuda_runtime.h>
#include <cuda_bf16.h>
#include <mma.h>
#include <cstdint>

using namespace nvcuda;

// Problem constants (fixed by the dataset)
#define NN 50000
#define EE 800000
#define TOT_E (EE + NN)   // edges + self loops = 850000

// ---------------- scratch (no allocations allowed) ----------------
__device__ __align__(16) float g_C1[NN * 256];   // [xl1 | xr1] per node (128+128)
__device__ __align__(16) float g_h [NN * 128];   // layer-1 output after ELU
__device__ __align__(16) float g_C2[NN * 128];   // [xl2 | xr2] per node (64+64)
__device__ __align__(16) __nv_bfloat16 g_Ah[NN * 128];   // A hi (bf16 split)
__device__ __align__(16) __nv_bfloat16 g_Al[NN * 128];   // A lo
__device__ __align__(16) __nv_bfloat16 g_Bh[256 * 128];  // W transposed [n][k] hi
__device__ __align__(16) __nv_bfloat16 g_Bl[256 * 128];  // W transposed [n][k] lo
__device__ int   g_deg[NN];
__device__ int   g_tmp[NN];
__device__ int   g_off[NN + 1];
__device__ int   g_cur[NN];
__device__ int   g_bsum[64];
__device__ int   g_bscan[64];
__device__ int   g_csr[TOT_E];
__device__ int   g_is64;          // 1 if edge_index is int64, 0 if int32

// ---------------- edge-index dtype handling ----------------
__global__ void k_detect(const void* __restrict__ ei) {
    if (threadIdx.x == 0 && blockIdx.x == 0) {
        const long long* p = (const long long*)ei;
        int ok = 1;
        for (int i = 0; i < 64; i++) {
            long long v = p[i];
            if (v < 0 || v >= NN) { ok = 0; break; }
        }
        g_is64 = ok;
    }
}

__device__ __forceinline__ int edge_at(const void* ei, int idx) {
    if (g_is64) return (int)((const long long*)ei)[idx];
    return ((const int*)ei)[idx];
}

// ---------------- CSR build ----------------
__global__ void k_init_deg() {
    int i = blockIdx.x * blockDim.x + threadIdx.x;
    if (i < NN) g_deg[i] = 1;   // self loop
}

__global__ void k_hist(const void* __restrict__ ei) {
    int e = blockIdx.x * blockDim.x + threadIdx.x;
    if (e < EE) {
        int d = edge_at(ei, EE + e);
        atomicAdd(&g_deg[d], 1);
    }
}

__global__ void k_scan1() {
    __shared__ int sh[1024];
    int t = threadIdx.x;
    int i = blockIdx.x * 1024 + t;
    int v = (i < NN) ? g_deg[i] : 0;
    sh[t] = v;
    __syncthreads();
    #pragma unroll
    for (int off = 1; off < 1024; off <<= 1) {
        int x = (t >= off) ? sh[t - off] : 0;
        __syncthreads();
        sh[t] += x;
        __syncthreads();
    }
    if (i < NN) g_tmp[i] = sh[t] - v;
    if (t == 1023) g_bsum[blockIdx.x] = sh[1023];
}

__global__ void k_scan2(int nb) {
    if (threadIdx.x == 0 && blockIdx.x == 0) {
        int run = 0;
        for (int b = 0; b < nb; b++) { g_bscan[b] = run; run += g_bsum[b]; }
    }
}

__global__ void k_scan3() {
    int i = blockIdx.x * 1024 + threadIdx.x;
    if (i < NN) {
        int off = g_tmp[i] + g_bscan[blockIdx.x];
        g_off[i] = off;
        g_cur[i] = off;
        if (i == NN - 1) g_off[NN] = off + g_deg[i];
    }
}

__global__ void k_scatter(const void* __restrict__ ei) {
    int id = blockIdx.x * blockDim.x + threadIdx.x;
    if (id >= TOT_E) return;
    int s, d;
    if (id < EE) { s = edge_at(ei, id); d = edge_at(ei, EE + id); }
    else         { s = d = id - EE; }
    int p = atomicAdd(&g_cur[d], 1);
    g_csr[p] = s;
}

// ---------------- precompute bf16 hi/lo splits ----------------
__device__ __forceinline__ void bf16_split(float v, __nv_bfloat16& h, __nv_bfloat16& l) {
    h = __float2bfloat16(v);
    l = __float2bfloat16(v - __bfloat162float(h));
}

__global__ void k_convA1(const float* __restrict__ A) {
    int i = blockIdx.x * blockDim.x + threadIdx.x;   // one per 4 elements
    if (i >= NN * 32) return;
    float4 v = *(const float4*)&A[i * 4];
    __nv_bfloat16 h[4], l[4];
    bf16_split(v.x, h[0], l[0]);
    bf16_split(v.y, h[1], l[1]);
    bf16_split(v.z, h[2], l[2]);
    bf16_split(v.w, h[3], l[3]);
    *(uint2*)&g_Ah[i * 4] = *(uint2*)h;
    *(uint2*)&g_Al[i * 4] = *(uint2*)l;
}

template <int LAYER>
__global__ void k_convW(const float* __restrict__ B0, const float* __restrict__ B1) {
    const int split = (LAYER == 1) ? 128 : 64;
    const int NB = 2 * split;
    int idx = blockIdx.x * blockDim.x + threadIdx.x;  // n fastest (coalesced W read)
    if (idx >= NB * 128) return;
    int n = idx % NB, k = idx / NB;
    const float* W = (n < split) ? B0 : B1;
    int wc = (n < split) ? n : n - split;
    float v = W[k * split + wc];
    __nv_bfloat16 h, l;
    bf16_split(v, h, l);
    g_Bh[n * 128 + k] = h;
    g_Bl[n * 128 + k] = l;
}

// ---------------- WMMA bf16 GEMM (preconverted operands) ----------------
#define GBM 128
#define GBN 128
#define GBK 32
#define GLDA 40
#define SM_A_BYTES (GBM * GLDA * 2)                 // 10240
#define SM_GEMM_TOTAL (4 * SM_A_BYTES + 16 * GBN * 4)   // 49152

template <int LAYER>
__global__ void __launch_bounds__(256)
k_gemm_mma(const float* __restrict__ bias0, const float* __restrict__ bias1)
{
    extern __shared__ char smem[];
    __nv_bfloat16* As_h = (__nv_bfloat16*)(smem);
    __nv_bfloat16* As_l = (__nv_bfloat16*)(smem + SM_A_BYTES);
    __nv_bfloat16* Bs_h = (__nv_bfloat16*)(smem + 2 * SM_A_BYTES);
    __nv_bfloat16* Bs_l = (__nv_bfloat16*)(smem + 3 * SM_A_BYTES);
    float* BiasT = (float*)(smem + 4 * SM_A_BYTES);   // [16][128], rows identical

    float* C        = (LAYER == 1) ? g_C1 : g_C2;
    const int split = (LAYER == 1) ? 128 : 64;
    const int NB    = 2 * split;

    int tid = threadIdx.x;
    int wid = tid >> 5;
    int lane = tid & 31;
    int rowBase = blockIdx.x * GBM;
    int colBase = blockIdx.y * GBN;
    int wm = (wid & 3) * 32;
    int wn = (wid >> 2) * 64;

    #pragma unroll
    for (int it = 0; it < 8; it++) {
        int idx = tid + it * 256;
        int c = idx & 127, r = idx >> 7;
        int col = colBase + c;
        float bv = (col < split) ? bias0[col] : bias1[col - split];
        BiasT[r * 128 + c] = bv;
    }
    __syncthreads();

    wmma::fragment<wmma::accumulator, 16, 16, 16, float> acc[2][4];
    #pragma unroll
    for (int m = 0; m < 2; m++)
        #pragma unroll
        for (int n = 0; n < 4; n++)
            wmma::load_matrix_sync(acc[m][n], &BiasT[wn + 16 * n], 128, wmma::mem_row_major);

    #pragma unroll
    for (int stage = 0; stage < 4; stage++) {
        int kb = stage * GBK;
        if (stage) __syncthreads();

        #pragma unroll
        for (int it = 0; it < 2; it++) {
            int idx = tid + it * 256;
            int kq = idx & 3, r = idx >> 2;
            int gr = rowBase + r;
            uint4 vh = make_uint4(0, 0, 0, 0), vl = make_uint4(0, 0, 0, 0);
            if (gr < NN) {
                vh = *(const uint4*)&g_Ah[gr * 128 + kb + kq * 8];
                vl = *(const uint4*)&g_Al[gr * 128 + kb + kq * 8];
            }
            *(uint4*)&As_h[r * GLDA + kq * 8] = vh;
            *(uint4*)&As_l[r * GLDA + kq * 8] = vl;
        }
        #pragma unroll
        for (int it = 0; it < 2; it++) {
            int idx = tid + it * 256;
            int kq = idx & 3, n = idx >> 2;
            int gn = colBase + n;
            uint4 vh = *(const uint4*)&g_Bh[gn * 128 + kb + kq * 8];
            uint4 vl = *(const uint4*)&g_Bl[gn * 128 + kb + kq * 8];
            *(uint4*)&Bs_h[n * GLDA + kq * 8] = vh;
            *(uint4*)&Bs_l[n * GLDA + kq * 8] = vl;
        }
        __syncthreads();

        #pragma unroll
        for (int ks = 0; ks < 2; ks++) {
            wmma::fragment<wmma::matrix_a, 16, 16, 16, __nv_bfloat16, wmma::row_major> ah[2], al[2];
            #pragma unroll
            for (int m = 0; m < 2; m++) {
                wmma::load_matrix_sync(ah[m], &As_h[(wm + 16 * m) * GLDA + ks * 16], GLDA);
                wmma::load_matrix_sync(al[m], &As_l[(wm + 16 * m) * GLDA + ks * 16], GLDA);
            }
            #pragma unroll
            for (int n = 0; n < 4; n++) {
                wmma::fragment<wmma::matrix_b, 16, 16, 16, __nv_bfloat16, wmma::col_major> bh, bl;
                wmma::load_matrix_sync(bh, &Bs_h[(wn + 16 * n) * GLDA + ks * 16], GLDA);
                wmma::load_matrix_sync(bl, &Bs_l[(wn + 16 * n) * GLDA + ks * 16], GLDA);
                #pragma unroll
                for (int m = 0; m < 2; m++) {
                    wmma::mma_sync(acc[m][n], ah[m], bh, acc[m][n]);
                    wmma::mma_sync(acc[m][n], ah[m], bl, acc[m][n]);
                    wmma::mma_sync(acc[m][n], al[m], bh, acc[m][n]);
                }
            }
        }
    }

    if (rowBase + GBM <= NN) {
        #pragma unroll
        for (int m = 0; m < 2; m++)
            #pragma unroll
            for (int n = 0; n < 4; n++) {
                int gr = rowBase + wm + 16 * m;
                wmma::store_matrix_sync(&C[(size_t)gr * NB + colBase + wn + 16 * n],
                                        acc[m][n], NB, wmma::mem_row_major);
            }
    } else {
        __syncthreads();
        float* scr = (float*)smem + wid * 16 * 20;
        #pragma unroll
        for (int m = 0; m < 2; m++)
            #pragma unroll
            for (int n = 0; n < 4; n++) {
                wmma::store_matrix_sync(scr, acc[m][n], 20, wmma::mem_row_major);
                __syncwarp();
                int r = lane >> 1, c0 = (lane & 1) * 8;
                int gr = rowBase + wm + 16 * m + r;
                if (gr < NN) {
                    int gc = colBase + wn + 16 * n + c0;
                    #pragma unroll
                    for (int j = 0; j < 8; j++)
                        C[(size_t)gr * NB + gc + j] = scr[r * 20 + c0 + j];
                }
                __syncwarp();
            }
    }
}

// ---------------- layer-1 edge pass (max-free softmax, unroll x4) ----------------
// warp per node; lane holds dims [4*lane,4*lane+4); head = lane>>2.
// Also emits bf16 hi/lo of h for the layer-2 GEMM (fused conversion).
__global__ void __launch_bounds__(256)
k_edge1(const float* __restrict__ att1, const float* __restrict__ bias1)
{
    int warp = (blockIdx.x * blockDim.x + threadIdx.x) >> 5;
    int lane = threadIdx.x & 31;
    if (warp >= NN) return;
    int node = warp;
    int sub = lane & 3;
    int head = lane >> 2;

    float4 av = *(const float4*)&att1[head * 16 + sub * 4];
    float4 xr = *(const float4*)&g_C1[node * 256 + 128 + lane * 4];

    float s = 0.f;
    float4 acc = make_float4(0.f, 0.f, 0.f, 0.f);

    int beg = g_off[node], end = g_off[node + 1];
    int i = beg;

    #define E1_ALPHA(xl, pout) do {                                              \
        float t0 = xl.x + xr.x, t1 = xl.y + xr.y, t2 = xl.z + xr.z, t3 = xl.w + xr.w; \
        t0 = t0 > 0.f ? t0 : 0.2f * t0;  t1 = t1 > 0.f ? t1 : 0.2f * t1;         \
        t2 = t2 > 0.f ? t2 : 0.2f * t2;  t3 = t3 > 0.f ? t3 : 0.2f * t3;         \
        pout = t0 * av.x + t1 * av.y + t2 * av.z + t3 * av.w;                    \
        pout += __shfl_xor_sync(0xffffffffu, pout, 1);                           \
        pout += __shfl_xor_sync(0xffffffffu, pout, 2);                           \
    } while (0)

    for (; i + 4 <= end; i += 4) {
        int s0 = g_csr[i], s1 = g_csr[i + 1], s2 = g_csr[i + 2], s3 = g_csr[i + 3];
        float4 x0 = *(const float4*)&g_C1[s0 * 256 + lane * 4];
        float4 x1 = *(const float4*)&g_C1[s1 * 256 + lane * 4];
        float4 x2 = *(const float4*)&g_C1[s2 * 256 + lane * 4];
        float4 x3 = *(const float4*)&g_C1[s3 * 256 + lane * 4];
        float p0, p1, p2, p3;
        E1_ALPHA(x0, p0); E1_ALPHA(x1, p1); E1_ALPHA(x2, p2); E1_ALPHA(x3, p3);
        float e0 = __expf(p0), e1 = __expf(p1), e2 = __expf(p2), e3 = __expf(p3);
        s += (e0 + e1) + (e2 + e3);
        acc.x += e0 * x0.x + e1 * x1.x + e2 * x2.x + e3 * x3.x;
        acc.y += e0 * x0.y + e1 * x1.y + e2 * x2.y + e3 * x3.y;
        acc.z += e0 * x0.z + e1 * x1.z + e2 * x2.z + e3 * x3.z;
        acc.w += e0 * x0.w + e1 * x1.w + e2 * x2.w + e3 * x3.w;
    }
    for (; i < end; i++) {
        int s0 = g_csr[i];
        float4 x0 = *(const float4*)&g_C1[s0 * 256 + lane * 4];
        float p0;
        E1_ALPHA(x0, p0);
        float e0 = __expf(p0);
        s += e0;
        acc.x += e0 * x0.x; acc.y += e0 * x0.y; acc.z += e0 * x0.z; acc.w += e0 * x0.w;
    }
    #undef E1_ALPHA

    float inv = 1.f / s;
    float4 bv = *(const float4*)&bias1[lane * 4];
    float o0 = acc.x * inv + bv.x;
    float o1 = acc.y * inv + bv.y;
    float o2 = acc.z * inv + bv.z;
    float o3 = acc.w * inv + bv.w;
    o0 = o0 > 0.f ? o0 : expm1f(o0);
    o1 = o1 > 0.f ? o1 : expm1f(o1);
    o2 = o2 > 0.f ? o2 : expm1f(o2);
    o3 = o3 > 0.f ? o3 : expm1f(o3);
    *(float4*)&g_h[node * 128 + lane * 4] = make_float4(o0, o1, o2, o3);

    // fused bf16 hi/lo conversion for layer-2 GEMM
    __nv_bfloat16 h[4], l[4];
    bf16_split(o0, h[0], l[0]);
    bf16_split(o1, h[1], l[1]);
    bf16_split(o2, h[2], l[2]);
    bf16_split(o3, h[3], l[3]);
    *(uint2*)&g_Ah[node * 128 + lane * 4] = *(uint2*)h;
    *(uint2*)&g_Al[node * 128 + lane * 4] = *(uint2*)l;
}

// ---------------- layer-2 edge pass (max-free softmax, unroll x4) ----------------
__global__ void __launch_bounds__(256)
k_edge2(const float* __restrict__ att2, const float* __restrict__ bias2,
        float* __restrict__ out)
{
    int warp = (blockIdx.x * blockDim.x + threadIdx.x) >> 5;
    int lane = threadIdx.x & 31;
    if (warp >= NN) return;
    int node = warp;

    float2 av = *(const float2*)&att2[lane * 2];
    float2 xr = *(const float2*)&g_C2[node * 128 + 64 + lane * 2];

    float s = 0.f;
    float2 acc = make_float2(0.f, 0.f);

    int beg = g_off[node], end = g_off[node + 1];
    int i = beg;

    #define E2_ALPHA(xl, pout) do {                                      \
        float t0 = xl.x + xr.x, t1 = xl.y + xr.y;                        \
        t0 = t0 > 0.f ? t0 : 0.2f * t0;  t1 = t1 > 0.f ? t1 : 0.2f * t1; \
        pout = t0 * av.x + t1 * av.y;                                    \
        pout += __shfl_xor_sync(0xffffffffu, pout, 1);                   \
        pout += __shfl_xor_sync(0xffffffffu, pout, 2);                   \
        pout += __shfl_xor_sync(0xffffffffu, pout, 4);                   \
        pout += __shfl_xor_sync(0xffffffffu, pout, 8);                   \
        pout += __shfl_xor_sync(0xffffffffu, pout, 16);                  \
    } while (0)

    for (; i + 4 <= end; i += 4) {
        int s0 = g_csr[i], s1 = g_csr[i + 1], s2 = g_csr[i + 2], s3 = g_csr[i + 3];
        float2 x0 = *(const float2*)&g_C2[s0 * 128 + lane * 2];
        float2 x1 = *(const float2*)&g_C2[s1 * 128 + lane * 2];
        float2 x2 = *(const float2*)&g_C2[s2 * 128 + lane * 2];
        float2 x3 = *(const float2*)&g_C2[s3 * 128 + lane * 2];
        float p0, p1, p2, p3;
        E2_ALPHA(x0, p0); E2_ALPHA(x1, p1); E2_ALPHA(x2, p2); E2_ALPHA(x3, p3);
        float e0 = __expf(p0), e1 = __expf(p1), e2 = __expf(p2), e3 = __expf(p3);
        s += (e0 + e1) + (e2 + e3);
        acc.x += e0 * x0.x + e1 * x1.x + e2 * x2.x + e3 * x3.x;
        acc.y += e0 * x0.y + e1 * x1.y + e2 * x2.y + e3 * x3.y;
    }
    for (; i < end; i++) {
        int s0 = g_csr[i];
        float2 x0 = *(const float2*)&g_C2[s0 * 128 + lane * 2];
        float p0;
        E2_ALPHA(x0, p0);
        float e0 = __expf(p0);
        s += e0;
        acc.x += e0 * x0.x; acc.y += e0 * x0.y;
    }
    #undef E2_ALPHA

    float inv = 1.f / s;
    float2 bv = *(const float2*)&bias2[lane * 2];
    float2 o;
    o.x = acc.x * inv + bv.x;
    o.y = acc.y * inv + bv.y;
    *(float2*)&out[node * 64 + lane * 2] = o;
}

// ---------------- launch ----------------
extern "C" void kernel_launch(void* const* d_in, const int* in_sizes, int n_in,
                              void* d_out, int out_size)
{
    const float* x     = (const float*)d_in[0];
    const void*  ei    = d_in[1];
    const float* W1l   = (const float*)d_in[2];
    const float* b1l   = (const float*)d_in[3];
    const float* W1r   = (const float*)d_in[4];
    const float* b1r   = (const float*)d_in[5];
    const float* att1  = (const float*)d_in[6];
    const float* bias1 = (const float*)d_in[7];
    const float* W2l   = (const float*)d_in[8];
    const float* b2l   = (const float*)d_in[9];
    const float* W2r   = (const float*)d_in[10];
    const float* b2r   = (const float*)d_in[11];
    const float* att2  = (const float*)d_in[12];
    const float* bias2 = (const float*)d_in[13];
    float* out = (float*)d_out;

    // CSR build
    k_detect<<<1, 32>>>(ei);
    k_init_deg<<<(NN + 255) / 256, 256>>>();
    k_hist<<<(EE + 255) / 256, 256>>>(ei);
    int nsb = (NN + 1023) / 1024;           // 49
    k_scan1<<<nsb, 1024>>>();
    k_scan2<<<1, 32>>>(nsb);
    k_scan3<<<nsb, 1024>>>();
    k_scatter<<<(TOT_E + 255) / 256, 256>>>(ei);

    // layer 1
    k_convA1<<<(NN * 32 + 255) / 256, 256>>>(x);
    k_convW<1><<<(256 * 128 + 255) / 256, 256>>>(W1l, W1r);
    {
        dim3 grid((NN + 127) / 128, 2);
        k_gemm_mma<1><<<grid, 256, SM_GEMM_TOTAL>>>(b1l, b1r);
    }
    k_edge1<<<(NN * 32 + 255) / 256, 256>>>(att1, bias1);  // writes g_h + bf16 split

    // layer 2
    k_convW<2><<<(128 * 128 + 255) / 256, 256>>>(W2l, W2r);
    {
        dim3 grid((NN + 127) / 128, 1);
        k_gemm_mma<2><<<grid, 256, SM_GEMM_TOTAL>>>(b2l, b2r);
    }
    k_edge2<<<(NN * 32 + 255) / 256, 256>>>(att2, bias2, out);

    (void)in_sizes; (void)n_in; (void)out_size;
}

// round 12
// speedup vs baseline: 1.4642x; 1.0328x over previous
#include <cuda_runtime.h>
#include <cuda_bf16.h>
#include <mma.h>
#include <cstdint>

using namespace nvcuda;

// Problem constants (fixed by the dataset)
#define NN 50000
#define EE 800000
#define TOT_E (EE + NN)   // edges + self loops = 850000

// ---------------- scratch (no allocations allowed) ----------------
__device__ __align__(16) float g_C1[NN * 256];   // [xl1 | xr1] per node (128+128)
__device__ __align__(16) float g_h [NN * 128];   // layer-1 output after ELU
__device__ __align__(16) float g_C2[NN * 128];   // [xl2 | xr2] per node (64+64)
__device__ __align__(16) __nv_bfloat16 g_Ah[NN * 128];   // A hi (bf16 split)
__device__ __align__(16) __nv_bfloat16 g_Al[NN * 128];   // A lo
__device__ __align__(16) __nv_bfloat16 g_Bh[256 * 128];  // layer-1 W transposed [n][k] hi
__device__ __align__(16) __nv_bfloat16 g_Bl[256 * 128];  // layer-1 W transposed [n][k] lo
__device__ __align__(16) __nv_bfloat16 g_Bh2[128 * 128]; // layer-2 W transposed hi
__device__ __align__(16) __nv_bfloat16 g_Bl2[128 * 128]; // layer-2 W transposed lo
__device__ int   g_deg[NN];
__device__ int   g_tmp[NN];
__device__ int   g_off[NN + 1];
__device__ int   g_cur[NN];
__device__ int   g_bsum[64];
__device__ int   g_bscan[64];
__device__ int   g_csr[TOT_E];
__device__ int   g_is64;          // 1 if edge_index is int64, 0 if int32

// ---------------- edge-index dtype handling ----------------
__global__ void k_detect(const void* __restrict__ ei) {
    if (threadIdx.x == 0 && blockIdx.x == 0) {
        const long long* p = (const long long*)ei;
        int ok = 1;
        for (int i = 0; i < 64; i++) {
            long long v = p[i];
            if (v < 0 || v >= NN) { ok = 0; break; }
        }
        g_is64 = ok;
    }
}

__device__ __forceinline__ int edge_at(const void* ei, int idx) {
    if (g_is64) return (int)((const long long*)ei)[idx];
    return ((const int*)ei)[idx];
}

// ---------------- CSR build ----------------
__global__ void k_init_deg() {
    int i = blockIdx.x * blockDim.x + threadIdx.x;
    if (i < NN) g_deg[i] = 1;   // self loop
}

__global__ void k_hist(const void* __restrict__ ei) {
    int e = blockIdx.x * blockDim.x + threadIdx.x;
    if (e < EE) {
        int d = edge_at(ei, EE + e);
        atomicAdd(&g_deg[d], 1);
    }
}

__global__ void k_scan1() {
    __shared__ int sh[1024];
    int t = threadIdx.x;
    int i = blockIdx.x * 1024 + t;
    int v = (i < NN) ? g_deg[i] : 0;
    sh[t] = v;
    __syncthreads();
    #pragma unroll
    for (int off = 1; off < 1024; off <<= 1) {
        int x = (t >= off) ? sh[t - off] : 0;
        __syncthreads();
        sh[t] += x;
        __syncthreads();
    }
    if (i < NN) g_tmp[i] = sh[t] - v;
    if (t == 1023) g_bsum[blockIdx.x] = sh[1023];
}

__global__ void k_scan2(int nb) {
    if (threadIdx.x == 0 && blockIdx.x == 0) {
        int run = 0;
        for (int b = 0; b < nb; b++) { g_bscan[b] = run; run += g_bsum[b]; }
    }
}

__global__ void k_scan3() {
    int i = blockIdx.x * 1024 + threadIdx.x;
    if (i < NN) {
        int off = g_tmp[i] + g_bscan[blockIdx.x];
        g_off[i] = off;
        g_cur[i] = off;
        if (i == NN - 1) g_off[NN] = off + g_deg[i];
    }
}

__global__ void k_scatter(const void* __restrict__ ei) {
    int id = blockIdx.x * blockDim.x + threadIdx.x;
    if (id >= TOT_E) return;
    int s, d;
    if (id < EE) { s = edge_at(ei, id); d = edge_at(ei, EE + id); }
    else         { s = d = id - EE; }
    int p = atomicAdd(&g_cur[d], 1);
    g_csr[p] = s;
}

// ---------------- precompute bf16 hi/lo splits ----------------
__device__ __forceinline__ void bf16_split(float v, __nv_bfloat16& h, __nv_bfloat16& l) {
    h = __float2bfloat16(v);
    l = __float2bfloat16(v - __bfloat162float(h));
}

__global__ void k_convA1(const float* __restrict__ A) {
    int i = blockIdx.x * blockDim.x + threadIdx.x;   // one per 4 elements
    if (i >= NN * 32) return;
    float4 v = *(const float4*)&A[i * 4];
    __nv_bfloat16 h[4], l[4];
    bf16_split(v.x, h[0], l[0]);
    bf16_split(v.y, h[1], l[1]);
    bf16_split(v.z, h[2], l[2]);
    bf16_split(v.w, h[3], l[3]);
    *(uint2*)&g_Ah[i * 4] = *(uint2*)h;
    *(uint2*)&g_Al[i * 4] = *(uint2*)l;
}

template <int LAYER>
__global__ void k_convW(const float* __restrict__ B0, const float* __restrict__ B1) {
    const int split = (LAYER == 1) ? 128 : 64;
    const int NB = 2 * split;
    __nv_bfloat16* Dh = (LAYER == 1) ? g_Bh : g_Bh2;
    __nv_bfloat16* Dl = (LAYER == 1) ? g_Bl : g_Bl2;
    int idx = blockIdx.x * blockDim.x + threadIdx.x;  // n fastest (coalesced W read)
    if (idx >= NB * 128) return;
    int n = idx % NB, k = idx / NB;
    const float* W = (n < split) ? B0 : B1;
    int wc = (n < split) ? n : n - split;
    float v = W[k * split + wc];
    __nv_bfloat16 h, l;
    bf16_split(v, h, l);
    Dh[n * 128 + k] = h;
    Dl[n * 128 + k] = l;
}

// ---------------- WMMA bf16 GEMM (preconverted operands) ----------------
#define GBM 128
#define GBN 128
#define GBK 32
#define GLDA 40
#define SM_A_BYTES (GBM * GLDA * 2)                 // 10240
#define SM_GEMM_TOTAL (4 * SM_A_BYTES + 16 * GBN * 4)   // 49152

template <int LAYER>
__global__ void __launch_bounds__(256)
k_gemm_mma(const float* __restrict__ bias0, const float* __restrict__ bias1)
{
    extern __shared__ char smem[];
    __nv_bfloat16* As_h = (__nv_bfloat16*)(smem);
    __nv_bfloat16* As_l = (__nv_bfloat16*)(smem + SM_A_BYTES);
    __nv_bfloat16* Bs_h = (__nv_bfloat16*)(smem + 2 * SM_A_BYTES);
    __nv_bfloat16* Bs_l = (__nv_bfloat16*)(smem + 3 * SM_A_BYTES);
    float* BiasT = (float*)(smem + 4 * SM_A_BYTES);   // [16][128], rows identical

    float* C        = (LAYER == 1) ? g_C1 : g_C2;
    const __nv_bfloat16* Wh = (LAYER == 1) ? g_Bh : g_Bh2;
    const __nv_bfloat16* Wl = (LAYER == 1) ? g_Bl : g_Bl2;
    const int split = (LAYER == 1) ? 128 : 64;
    const int NB    = 2 * split;

    int tid = threadIdx.x;
    int wid = tid >> 5;
    int lane = tid & 31;
    int rowBase = blockIdx.x * GBM;
    int colBase = blockIdx.y * GBN;
    int wm = (wid & 3) * 32;
    int wn = (wid >> 2) * 64;

    #pragma unroll
    for (int it = 0; it < 8; it++) {
        int idx = tid + it * 256;
        int c = idx & 127, r = idx >> 7;
        int col = colBase + c;
        float bv = (col < split) ? bias0[col] : bias1[col - split];
        BiasT[r * 128 + c] = bv;
    }
    __syncthreads();

    wmma::fragment<wmma::accumulator, 16, 16, 16, float> acc[2][4];
    #pragma unroll
    for (int m = 0; m < 2; m++)
        #pragma unroll
        for (int n = 0; n < 4; n++)
            wmma::load_matrix_sync(acc[m][n], &BiasT[wn + 16 * n], 128, wmma::mem_row_major);

    #pragma unroll
    for (int stage = 0; stage < 4; stage++) {
        int kb = stage * GBK;
        if (stage) __syncthreads();

        #pragma unroll
        for (int it = 0; it < 2; it++) {
            int idx = tid + it * 256;
            int kq = idx & 3, r = idx >> 2;
            int gr = rowBase + r;
            uint4 vh = make_uint4(0, 0, 0, 0), vl = make_uint4(0, 0, 0, 0);
            if (gr < NN) {
                vh = *(const uint4*)&g_Ah[gr * 128 + kb + kq * 8];
                vl = *(const uint4*)&g_Al[gr * 128 + kb + kq * 8];
            }
            *(uint4*)&As_h[r * GLDA + kq * 8] = vh;
            *(uint4*)&As_l[r * GLDA + kq * 8] = vl;
        }
        #pragma unroll
        for (int it = 0; it < 2; it++) {
            int idx = tid + it * 256;
            int kq = idx & 3, n = idx >> 2;
            int gn = colBase + n;
            uint4 vh = *(const uint4*)&Wh[gn * 128 + kb + kq * 8];
            uint4 vl = *(const uint4*)&Wl[gn * 128 + kb + kq * 8];
            *(uint4*)&Bs_h[n * GLDA + kq * 8] = vh;
            *(uint4*)&Bs_l[n * GLDA + kq * 8] = vl;
        }
        __syncthreads();

        #pragma unroll
        for (int ks = 0; ks < 2; ks++) {
            wmma::fragment<wmma::matrix_a, 16, 16, 16, __nv_bfloat16, wmma::row_major> ah[2], al[2];
            #pragma unroll
            for (int m = 0; m < 2; m++) {
                wmma::load_matrix_sync(ah[m], &As_h[(wm + 16 * m) * GLDA + ks * 16], GLDA);
                wmma::load_matrix_sync(al[m], &As_l[(wm + 16 * m) * GLDA + ks * 16], GLDA);
            }
            #pragma unroll
            for (int n = 0; n < 4; n++) {
                wmma::fragment<wmma::matrix_b, 16, 16, 16, __nv_bfloat16, wmma::col_major> bh, bl;
                wmma::load_matrix_sync(bh, &Bs_h[(wn + 16 * n) * GLDA + ks * 16], GLDA);
                wmma::load_matrix_sync(bl, &Bs_l[(wn + 16 * n) * GLDA + ks * 16], GLDA);
                #pragma unroll
                for (int m = 0; m < 2; m++) {
                    wmma::mma_sync(acc[m][n], ah[m], bh, acc[m][n]);
                    wmma::mma_sync(acc[m][n], ah[m], bl, acc[m][n]);
                    wmma::mma_sync(acc[m][n], al[m], bh, acc[m][n]);
                }
            }
        }
    }

    if (rowBase + GBM <= NN) {
        #pragma unroll
        for (int m = 0; m < 2; m++)
            #pragma unroll
            for (int n = 0; n < 4; n++) {
                int gr = rowBase + wm + 16 * m;
                wmma::store_matrix_sync(&C[(size_t)gr * NB + colBase + wn + 16 * n],
                                        acc[m][n], NB, wmma::mem_row_major);
            }
    } else {
        __syncthreads();
        float* scr = (float*)smem + wid * 16 * 20;
        #pragma unroll
        for (int m = 0; m < 2; m++)
            #pragma unroll
            for (int n = 0; n < 4; n++) {
                wmma::store_matrix_sync(scr, acc[m][n], 20, wmma::mem_row_major);
                __syncwarp();
                int r = lane >> 1, c0 = (lane & 1) * 8;
                int gr = rowBase + wm + 16 * m + r;
                if (gr < NN) {
                    int gc = colBase + wn + 16 * n + c0;
                    #pragma unroll
                    for (int j = 0; j < 8; j++)
                        C[(size_t)gr * NB + gc + j] = scr[r * 20 + c0 + j];
                }
                __syncwarp();
            }
    }
}

// ---------------- layer-1 edge pass (max-free softmax, unroll x8) ----------------
__global__ void __launch_bounds__(256)
k_edge1(const float* __restrict__ att1, const float* __restrict__ bias1)
{
    int warp = (blockIdx.x * blockDim.x + threadIdx.x) >> 5;
    int lane = threadIdx.x & 31;
    if (warp >= NN) return;
    int node = warp;
    int sub = lane & 3;
    int head = lane >> 2;

    float4 av = *(const float4*)&att1[head * 16 + sub * 4];
    float4 xr = *(const float4*)&g_C1[node * 256 + 128 + lane * 4];

    float s = 0.f;
    float4 acc = make_float4(0.f, 0.f, 0.f, 0.f);

    int beg = g_off[node], end = g_off[node + 1];
    int i = beg;

    #define E1_ALPHA(xl, pout) do {                                              \
        float t0 = xl.x + xr.x, t1 = xl.y + xr.y, t2 = xl.z + xr.z, t3 = xl.w + xr.w; \
        t0 = t0 > 0.f ? t0 : 0.2f * t0;  t1 = t1 > 0.f ? t1 : 0.2f * t1;         \
        t2 = t2 > 0.f ? t2 : 0.2f * t2;  t3 = t3 > 0.f ? t3 : 0.2f * t3;         \
        pout = t0 * av.x + t1 * av.y + t2 * av.z + t3 * av.w;                    \
        pout += __shfl_xor_sync(0xffffffffu, pout, 1);                           \
        pout += __shfl_xor_sync(0xffffffffu, pout, 2);                           \
    } while (0)

    for (; i + 8 <= end; i += 8) {
        float4 xv[8]; float p[8];
        #pragma unroll
        for (int u = 0; u < 8; u++)
            xv[u] = *(const float4*)&g_C1[g_csr[i + u] * 256 + lane * 4];
        #pragma unroll
        for (int u = 0; u < 8; u++) E1_ALPHA(xv[u], p[u]);
        #pragma unroll
        for (int u = 0; u < 8; u++) {
            float e = __expf(p[u]);
            s += e;
            acc.x += e * xv[u].x; acc.y += e * xv[u].y;
            acc.z += e * xv[u].z; acc.w += e * xv[u].w;
        }
    }
    for (; i + 4 <= end; i += 4) {
        float4 xv[4]; float p[4];
        #pragma unroll
        for (int u = 0; u < 4; u++)
            xv[u] = *(const float4*)&g_C1[g_csr[i + u] * 256 + lane * 4];
        #pragma unroll
        for (int u = 0; u < 4; u++) E1_ALPHA(xv[u], p[u]);
        #pragma unroll
        for (int u = 0; u < 4; u++) {
            float e = __expf(p[u]);
            s += e;
            acc.x += e * xv[u].x; acc.y += e * xv[u].y;
            acc.z += e * xv[u].z; acc.w += e * xv[u].w;
        }
    }
    for (; i < end; i++) {
        float4 x0 = *(const float4*)&g_C1[g_csr[i] * 256 + lane * 4];
        float p0;
        E1_ALPHA(x0, p0);
        float e0 = __expf(p0);
        s += e0;
        acc.x += e0 * x0.x; acc.y += e0 * x0.y; acc.z += e0 * x0.z; acc.w += e0 * x0.w;
    }
    #undef E1_ALPHA

    float inv = 1.f / s;
    float4 bv = *(const float4*)&bias1[lane * 4];
    float o0 = acc.x * inv + bv.x;
    float o1 = acc.y * inv + bv.y;
    float o2 = acc.z * inv + bv.z;
    float o3 = acc.w * inv + bv.w;
    o0 = o0 > 0.f ? o0 : expm1f(o0);
    o1 = o1 > 0.f ? o1 : expm1f(o1);
    o2 = o2 > 0.f ? o2 : expm1f(o2);
    o3 = o3 > 0.f ? o3 : expm1f(o3);
    *(float4*)&g_h[node * 128 + lane * 4] = make_float4(o0, o1, o2, o3);

    // fused bf16 hi/lo conversion for layer-2 GEMM
    __nv_bfloat16 h[4], l[4];
    bf16_split(o0, h[0], l[0]);
    bf16_split(o1, h[1], l[1]);
    bf16_split(o2, h[2], l[2]);
    bf16_split(o3, h[3], l[3]);
    *(uint2*)&g_Ah[node * 128 + lane * 4] = *(uint2*)h;
    *(uint2*)&g_Al[node * 128 + lane * 4] = *(uint2*)l;
}

// ---------------- layer-2 edge pass (max-free softmax, unroll x8) ----------------
__global__ void __launch_bounds__(256)
k_edge2(const float* __restrict__ att2, const float* __restrict__ bias2,
        float* __restrict__ out)
{
    int warp = (blockIdx.x * blockDim.x + threadIdx.x) >> 5;
    int lane = threadIdx.x & 31;
    if (warp >= NN) return;
    int node = warp;

    float2 av = *(const float2*)&att2[lane * 2];
    float2 xr = *(const float2*)&g_C2[node * 128 + 64 + lane * 2];

    float s = 0.f;
    float2 acc = make_float2(0.f, 0.f);

    int beg = g_off[node], end = g_off[node + 1];
    int i = beg;

    #define E2_ALPHA(xl, pout) do {                                      \
        float t0 = xl.x + xr.x, t1 = xl.y + xr.y;                        \
        t0 = t0 > 0.f ? t0 : 0.2f * t0;  t1 = t1 > 0.f ? t1 : 0.2f * t1; \
        pout = t0 * av.x + t1 * av.y;                                    \
        pout += __shfl_xor_sync(0xffffffffu, pout, 1);                   \
        pout += __shfl_xor_sync(0xffffffffu, pout, 2);                   \
        pout += __shfl_xor_sync(0xffffffffu, pout, 4);                   \
        pout += __shfl_xor_sync(0xffffffffu, pout, 8);                   \
        pout += __shfl_xor_sync(0xffffffffu, pout, 16);                  \
    } while (0)

    for (; i + 8 <= end; i += 8) {
        float2 xv[8]; float p[8];
        #pragma unroll
        for (int u = 0; u < 8; u++)
            xv[u] = *(const float2*)&g_C2[g_csr[i + u] * 128 + lane * 2];
        #pragma unroll
        for (int u = 0; u < 8; u++) E2_ALPHA(xv[u], p[u]);
        #pragma unroll
        for (int u = 0; u < 8; u++) {
            float e = __expf(p[u]);
            s += e;
            acc.x += e * xv[u].x; acc.y += e * xv[u].y;
        }
    }
    for (; i + 4 <= end; i += 4) {
        float2 xv[4]; float p[4];
        #pragma unroll
        for (int u = 0; u < 4; u++)
            xv[u] = *(const float2*)&g_C2[g_csr[i + u] * 128 + lane * 2];
        #pragma unroll
        for (int u = 0; u < 4; u++) E2_ALPHA(xv[u], p[u]);
        #pragma unroll
        for (int u = 0; u < 4; u++) {
            float e = __expf(p[u]);
            s += e;
            acc.x += e * xv[u].x; acc.y += e * xv[u].y;
        }
    }
    for (; i < end; i++) {
        float2 x0 = *(const float2*)&g_C2[g_csr[i] * 128 + lane * 2];
        float p0;
        E2_ALPHA(x0, p0);
        float e0 = __expf(p0);
        s += e0;
        acc.x += e0 * x0.x; acc.y += e0 * x0.y;
    }
    #undef E2_ALPHA

    float inv = 1.f / s;
    float2 bv = *(const float2*)&bias2[lane * 2];
    float2 o;
    o.x = acc.x * inv + bv.x;
    o.y = acc.y * inv + bv.y;
    *(float2*)&out[node * 64 + lane * 2] = o;
}

// ---------------- launch ----------------
extern "C" void kernel_launch(void* const* d_in, const int* in_sizes, int n_in,
                              void* d_out, int out_size)
{
    const float* x     = (const float*)d_in[0];
    const void*  ei    = d_in[1];
    const float* W1l   = (const float*)d_in[2];
    const float* b1l   = (const float*)d_in[3];
    const float* W1r   = (const float*)d_in[4];
    const float* b1r   = (const float*)d_in[5];
    const float* att1  = (const float*)d_in[6];
    const float* bias1 = (const float*)d_in[7];
    const float* W2l   = (const float*)d_in[8];
    const float* b2l   = (const float*)d_in[9];
    const float* W2r   = (const float*)d_in[10];
    const float* b2r   = (const float*)d_in[11];
    const float* att2  = (const float*)d_in[12];
    const float* bias2 = (const float*)d_in[13];
    float* out = (float*)d_out;

    // Lazy one-time creation (first call is the non-captured correctness run)
    static cudaStream_t s2 = nullptr;
    static cudaEvent_t evA = nullptr, evB = nullptr;
    static bool tried = false;
    if (!tried) {
        tried = true;
        if (cudaStreamCreateWithFlags(&s2, cudaStreamNonBlocking) != cudaSuccess) { s2 = nullptr; }
        if (s2) {
            if (cudaEventCreateWithFlags(&evA, cudaEventDisableTiming) != cudaSuccess ||
                cudaEventCreateWithFlags(&evB, cudaEventDisableTiming) != cudaSuccess) {
                s2 = nullptr;
            }
        }
    }
    cudaStream_t cs = s2 ? s2 : (cudaStream_t)0;

    // Fork: CSR build on cs, concurrent with conv+GEMM1 on stream 0
    if (s2) { cudaEventRecord(evA, 0); cudaStreamWaitEvent(s2, evA, 0); }

    k_detect <<<1, 32, 0, cs>>>(ei);
    k_init_deg<<<(NN + 255) / 256, 256, 0, cs>>>();
    k_hist   <<<(EE + 255) / 256, 256, 0, cs>>>(ei);
    int nsb = (NN + 1023) / 1024;           // 49
    k_scan1  <<<nsb, 1024, 0, cs>>>();
    k_scan2  <<<1, 32, 0, cs>>>(nsb);
    k_scan3  <<<nsb, 1024, 0, cs>>>();
    k_scatter<<<(TOT_E + 255) / 256, 256, 0, cs>>>(ei);

    // Main chain on stream 0 (layer-2 weights go to their OWN buffers -> no WAR hazard)
    k_convA1 <<<(NN * 32 + 255) / 256, 256>>>(x);
    k_convW<1><<<(256 * 128 + 255) / 256, 256>>>(W1l, W1r);
    k_convW<2><<<(128 * 128 + 255) / 256, 256>>>(W2l, W2r);
    {
        dim3 grid((NN + 127) / 128, 2);
        k_gemm_mma<1><<<grid, 256, SM_GEMM_TOTAL>>>(b1l, b1r);
    }

    // Join: edge1 needs CSR
    if (s2) { cudaEventRecord(evB, s2); cudaStreamWaitEvent(0, evB, 0); }

    k_edge1<<<(NN * 32 + 255) / 256, 256>>>(att1, bias1);  // writes g_h + bf16 split

    {
        dim3 grid((NN + 127) / 128, 1);
        k_gemm_mma<2><<<grid, 256, SM_GEMM_TOTAL>>>(b2l, b2r);
    }
    k_edge2<<<(NN * 32 + 255) / 256, 256>>>(att2, bias2, out);

    (void)in_sizes; (void)n_in; (void)out_size;
}